// round 13
// baseline (speedup 1.0000x reference)
#include <cuda_runtime.h>
#include <cuda_bf16.h>
#include <cstdint>
#include <math.h>

#define Nn 131072
#define Dd 512
#define Kk 1024
#define ALPHA 32.0f
#define EPS 1e-5f

// GEMM tiling: CTA 128x256, warp tile 64x64 (2x4 warps)
#define BM 128
#define BN 256
#define KC 32                  // K elems per chunk
#define LDSB 80                // smem row stride bytes (64 data + 16 pad)
#define PLANE_A (128 * LDSB)   // 10240 B
#define PLANE_B (256 * LDSB)   // 20480 B
#define OFF_AHI 0
#define OFF_ALO PLANE_A
#define OFF_BHI (2 * PLANE_A)
#define OFF_BLO (2 * PLANE_A + PLANE_B)
#define SSTAGE (2 * PLANE_A + 2 * PLANE_B)   // 61440 B
#define NSTAGE 3
#define EPI_LD 260             // epilogue f32 row stride (1040 B, 16B-aligned)
#define DSMEM (NSTAGE * SSTAGE)   // 184320 B (epi 128x260x4 = 133120 fits)

// Scratch (only referenced from DEVICE code)
__device__ float g_x2[Nn];
__device__ float g_c2[Kk];
__device__ __nv_bfloat16 g_xa_hi[(size_t)Nn * Dd];   // xn hi/lo (N x D)
__device__ __nv_bfloat16 g_xa_lo[(size_t)Nn * Dd];
__device__ __nv_bfloat16 g_cb_hi[(size_t)Kk * Dd];   // C hi/lo (K x D)
__device__ __nv_bfloat16 g_cb_lo[(size_t)Kk * Dd];
__device__ __nv_bfloat16 g_ct_hi[(size_t)Dd * Kk];   // C^T hi/lo (D x K)
__device__ __nv_bfloat16 g_ct_lo[(size_t)Dd * Kk];
__device__ __nv_bfloat16 g_sa_hi[(size_t)Nn * Kk];   // soft hi/lo (N x K)
__device__ __nv_bfloat16 g_sa_lo[(size_t)Nn * Kk];

// ───────── helpers ─────────
__device__ __forceinline__ uint32_t smem_u32(const void* p) {
    uint32_t a;
    asm("{ .reg .u64 t; cvta.to.shared.u64 t, %1; cvt.u32.u64 %0, t; }" : "=r"(a) : "l"(p));
    return a;
}
#define CP_ASYNC16(dst, src) \
    asm volatile("cp.async.cg.shared.global [%0], [%1], 16;" :: "r"(dst), "l"(src))
#define CP_COMMIT() asm volatile("cp.async.commit_group;" ::: "memory")
#define CP_WAIT(n)  asm volatile("cp.async.wait_group %0;" :: "n"(n) : "memory")

__device__ __forceinline__ void mma16816(float* c, uint32_t a0, uint32_t a1, uint32_t a2,
                                         uint32_t a3, uint32_t b0, uint32_t b1) {
    asm volatile("mma.sync.aligned.m16n8k16.row.col.f32.bf16.bf16.f32 "
                 "{%0,%1,%2,%3}, {%4,%5,%6,%7}, {%8,%9}, {%0,%1,%2,%3};"
                 : "+f"(c[0]), "+f"(c[1]), "+f"(c[2]), "+f"(c[3])
                 : "r"(a0), "r"(a1), "r"(a2), "r"(a3), "r"(b0), "r"(b1));
}
// bf16 hi/lo split of 4 floats
__device__ __forceinline__ void split4(float4 v, uint2& h, uint2& l) {
    __nv_bfloat16 h0 = __float2bfloat16(v.x), h1 = __float2bfloat16(v.y);
    __nv_bfloat16 h2 = __float2bfloat16(v.z), h3 = __float2bfloat16(v.w);
    __nv_bfloat16 l0 = __float2bfloat16(v.x - __bfloat162float(h0));
    __nv_bfloat16 l1 = __float2bfloat16(v.y - __bfloat162float(h1));
    __nv_bfloat16 l2 = __float2bfloat16(v.z - __bfloat162float(h2));
    __nv_bfloat16 l3 = __float2bfloat16(v.w - __bfloat162float(h3));
    __nv_bfloat162 a = __halves2bfloat162(h0, h1), b = __halves2bfloat162(h2, h3);
    __nv_bfloat162 c = __halves2bfloat162(l0, l1), d = __halves2bfloat162(l2, l3);
    h.x = *(uint32_t*)&a; h.y = *(uint32_t*)&b;
    l.x = *(uint32_t*)&c; l.y = *(uint32_t*)&d;
}

__device__ __forceinline__ float block_reduce(float v, float* sm, int op) {
    int lane = threadIdx.x & 31, wid = threadIdx.x >> 5;
    #pragma unroll
    for (int o = 16; o; o >>= 1) {
        float t = __shfl_xor_sync(0xffffffffu, v, o);
        v = op ? fminf(v, t) : (v + t);
    }
    if (lane == 0) sm[wid] = v;
    __syncthreads();
    int nw = blockDim.x >> 5;
    if (wid == 0) {
        float r = (lane < nw) ? sm[lane] : (op ? 3.4e38f : 0.0f);
        #pragma unroll
        for (int o = 16; o; o >>= 1) {
            float t = __shfl_xor_sync(0xffffffffu, r, o);
            r = op ? fminf(r, t) : (r + t);
        }
        if (lane == 0) sm[0] = r;
    }
    __syncthreads();
    float r = sm[0];
    __syncthreads();
    return r;
}

// ───────── layernorm → bf16 hi/lo + ||xn||² ─────────
__global__ void ln_kernel(const float* __restrict__ x, const float* __restrict__ w,
                          const float* __restrict__ b) {
    __shared__ float sm[32];
    size_t row = blockIdx.x;
    int t = threadIdx.x;
    float4 v = ((const float4*)(x + row * Dd))[t];
    float s = block_reduce(v.x + v.y + v.z + v.w, sm, 0);
    float mean = s * (1.0f / Dd);
    float d0 = v.x - mean, d1 = v.y - mean, d2 = v.z - mean, d3 = v.w - mean;
    float sq = block_reduce(d0 * d0 + d1 * d1 + d2 * d2 + d3 * d3, sm, 0);
    float inv = 1.0f / (sqrtf(sq * (1.0f / Dd)) + EPS);
    float4 wv = ((const float4*)w)[t];
    float4 bv = ((const float4*)b)[t];
    float4 o;
    o.x = d0 * inv * wv.x + bv.x;  o.y = d1 * inv * wv.y + bv.y;
    o.z = d2 * inv * wv.z + bv.z;  o.w = d3 * inv * wv.w + bv.w;
    float n2 = block_reduce(o.x * o.x + o.y * o.y + o.z * o.z + o.w * o.w, sm, 0);
    if (t == 0) g_x2[row] = n2;
    uint2 h, l;
    split4(o, h, l);
    ((uint2*)(g_xa_hi + row * Dd))[t] = h;
    ((uint2*)(g_xa_lo + row * Dd))[t] = l;
}

// ───────── center norms + C hi/lo ─────────
__global__ void c2_kernel(const float* __restrict__ C) {
    __shared__ float sm[32];
    size_t row = blockIdx.x;
    int t = threadIdx.x;
    float4 v = ((const float4*)(C + row * Dd))[t];
    float s = block_reduce(v.x * v.x + v.y * v.y + v.z * v.z + v.w * v.w, sm, 0);
    if (t == 0) g_c2[row] = s;
    uint2 h, l;
    split4(v, h, l);
    ((uint2*)(g_cb_hi + row * Dd))[t] = h;
    ((uint2*)(g_cb_lo + row * Dd))[t] = l;
}

// ───────── transpose C → C^T hi/lo (D x K) ─────────
__global__ void transpose_c(const float* __restrict__ C) {
    __shared__ float t[32][33];
    int x = blockIdx.x * 32 + threadIdx.x;   // d
    int y = blockIdx.y * 32 + threadIdx.y;   // k
    #pragma unroll
    for (int j = 0; j < 4; j++)
        t[threadIdx.y + j * 8][threadIdx.x] = C[(size_t)(y + j * 8) * Dd + x];
    __syncthreads();
    int x2 = blockIdx.y * 32 + threadIdx.x;  // k
    int y2 = blockIdx.x * 32 + threadIdx.y;  // d
    #pragma unroll
    for (int j = 0; j < 4; j++) {
        float v = t[threadIdx.x][threadIdx.y + j * 8];
        __nv_bfloat16 hi = __float2bfloat16(v);
        __nv_bfloat16 lo = __float2bfloat16(v - __bfloat162float(hi));
        g_ct_hi[(size_t)(y2 + j * 8) * Kk + x2] = hi;
        g_ct_lo[(size_t)(y2 + j * 8) * Kk + x2] = lo;
    }
}

// ───────── HMMA bf16x3 GEMM, 64x64 warp tiles, 3-stage cp.async ─────────
// MODE 0 (dist): A = g_xa (N x D), B = g_cb (K x D), KTOT=512, sqrt epilogue, ldo=Kk
// MODE 1 (rec):  A = g_sa (N x K), B = g_ct (D x K), KTOT=1024, identity, ldo=Dd
template <int MODE>
__global__ void __launch_bounds__(256, 1)
mma_gemm(float* __restrict__ out) {
    constexpr int KTOT = (MODE == 0) ? Dd : Kk;
    constexpr int LDAB = (MODE == 0) ? Dd : Kk;
    constexpr int LDO  = (MODE == 0) ? Kk : Dd;
    const __nv_bfloat16* Ah = (MODE == 0) ? g_xa_hi : g_sa_hi;
    const __nv_bfloat16* Al = (MODE == 0) ? g_xa_lo : g_sa_lo;
    const __nv_bfloat16* Bh = (MODE == 0) ? g_cb_hi : g_ct_hi;
    const __nv_bfloat16* Bl = (MODE == 0) ? g_cb_lo : g_ct_lo;

    extern __shared__ char smc[];
    const uint32_t sbase = smem_u32(smc);
    const int tid = threadIdx.x;
    const int wid = tid >> 5, lane = tid & 31;
    const int g = lane >> 2, tig = lane & 3;
    const int wm = wid & 1, wn = wid >> 1;       // warp tile: 64 x 64 (wn in 0..3)
    const int bm = blockIdx.y * BM;
    const int bn = blockIdx.x * BN;
    constexpr int NC = KTOT / KC;

    float acc[4][8][4];
    #pragma unroll
    for (int i = 0; i < 4; i++)
        #pragma unroll
        for (int j = 0; j < 8; j++)
            #pragma unroll
            for (int q = 0; q < 4; q++) acc[i][j][q] = 0.0f;

    // cp.async: 12 x 16B per thread covering Ahi/Alo (128 rows) + Bhi/Blo (256 rows)
    auto prefetch = [&](int c) {
        uint32_t sb = sbase + (uint32_t)(c % NSTAGE) * SSTAGE;
        int kc = c * KC;
        #pragma unroll
        for (int i = 0; i < 12; i++) {
            int idx = tid + i * 256;                 // 0..3071
            int rg = idx >> 2, seg = idx & 3;        // row-group 0..767
            const __nv_bfloat16* src;
            uint32_t dst;
            if (rg < 256) {                          // A planes: 128 hi + 128 lo
                int pl = rg >> 7, row = rg & 127;
                dst = sb + (pl ? OFF_ALO : OFF_AHI) + (uint32_t)row * LDSB + seg * 16;
                src = (pl ? Al : Ah) + (size_t)(bm + row) * LDAB + kc + seg * 8;
            } else {                                 // B planes: 256 hi + 256 lo
                int rb = rg - 256;
                int pl = rb >> 8, row = rb & 255;
                dst = sb + (pl ? OFF_BLO : OFF_BHI) + (uint32_t)row * LDSB + seg * 16;
                src = (pl ? Bl : Bh) + (size_t)(bn + row) * LDAB + kc + seg * 8;
            }
            CP_ASYNC16(dst, src);
        }
        CP_COMMIT();
    };

    prefetch(0);
    prefetch(1);

    for (int c = 0; c < NC; c++) {
        CP_WAIT(1);               // stage c resident (one group may be in flight)
        __syncthreads();          // all warps past compute c-1 before reuse of its stage
        if (c + 2 < NC) prefetch(c + 2);

        const char* stp = smc + (c % NSTAGE) * SSTAGE;
        #pragma unroll
        for (int ks = 0; ks < 2; ks++) {
            // B fragments resident for this ks (32 regs)
            uint32_t bh[8][2], bl[8][2];
            #pragma unroll
            for (int fn = 0; fn < 8; fn++) {
                const char* br = stp + OFF_BHI + (wn * 64 + fn * 8 + g) * LDSB + ks * 32 + tig * 4;
                bh[fn][0] = *(const uint32_t*)(br);
                bh[fn][1] = *(const uint32_t*)(br + 16);
                bl[fn][0] = *(const uint32_t*)(br + PLANE_B);
                bl[fn][1] = *(const uint32_t*)(br + PLANE_B + 16);
            }
            // fm pairs; 3 compensation passes pass-outer (16 independent accs per pass)
            #pragma unroll
            for (int fp = 0; fp < 2; fp++) {
                uint32_t ah[2][4], al[2][4];
                #pragma unroll
                for (int f = 0; f < 2; f++) {
                    int fm = fp * 2 + f;
                    const char* ar = stp + OFF_AHI + (wm * 64 + fm * 16 + g) * LDSB + ks * 32 + tig * 4;
                    ah[f][0] = *(const uint32_t*)(ar);
                    ah[f][1] = *(const uint32_t*)(ar + 8 * LDSB);
                    ah[f][2] = *(const uint32_t*)(ar + 16);
                    ah[f][3] = *(const uint32_t*)(ar + 8 * LDSB + 16);
                    al[f][0] = *(const uint32_t*)(ar + PLANE_A);
                    al[f][1] = *(const uint32_t*)(ar + PLANE_A + 8 * LDSB);
                    al[f][2] = *(const uint32_t*)(ar + PLANE_A + 16);
                    al[f][3] = *(const uint32_t*)(ar + PLANE_A + 8 * LDSB + 16);
                }
                #pragma unroll
                for (int f = 0; f < 2; f++)
                    #pragma unroll
                    for (int fn = 0; fn < 8; fn++)
                        mma16816(acc[fp * 2 + f][fn], ah[f][0], ah[f][1], ah[f][2], ah[f][3],
                                 bh[fn][0], bh[fn][1]);
                #pragma unroll
                for (int f = 0; f < 2; f++)
                    #pragma unroll
                    for (int fn = 0; fn < 8; fn++)
                        mma16816(acc[fp * 2 + f][fn], ah[f][0], ah[f][1], ah[f][2], ah[f][3],
                                 bl[fn][0], bl[fn][1]);
                #pragma unroll
                for (int f = 0; f < 2; f++)
                    #pragma unroll
                    for (int fn = 0; fn < 8; fn++)
                        mma16816(acc[fp * 2 + f][fn], al[f][0], al[f][1], al[f][2], al[f][3],
                                 bh[fn][0], bh[fn][1]);
            }
        }
    }

    CP_WAIT(0);
    __syncthreads();   // all warps done before smem reuse

    // epilogue: stage into smem (stride EPI_LD f32), then coalesced out
    float* epi = (float*)smc;
    #pragma unroll
    for (int fm = 0; fm < 4; fm++) {
        int r0 = wm * 64 + fm * 16 + g;
        #pragma unroll
        for (int fn = 0; fn < 8; fn++) {
            int cc = wn * 64 + fn * 8 + 2 * tig;
            *(float2*)&epi[r0 * EPI_LD + cc]       = make_float2(acc[fm][fn][0], acc[fm][fn][1]);
            *(float2*)&epi[(r0 + 8) * EPI_LD + cc] = make_float2(acc[fm][fn][2], acc[fm][fn][3]);
        }
    }
    __syncthreads();
    #pragma unroll
    for (int i = 0; i < 32; i++) {
        int idx = tid + i * 256;
        int row = idx >> 6, c4 = (idx & 63) * 4;
        float4 v = *(float4*)&epi[row * EPI_LD + c4];
        if (MODE == 0) {
            float x2v = g_x2[bm + row];
            v.x = sqrtf(fmaxf(x2v + g_c2[bn + c4 + 0] - 2.0f * v.x, 0.0f));
            v.y = sqrtf(fmaxf(x2v + g_c2[bn + c4 + 1] - 2.0f * v.y, 0.0f));
            v.z = sqrtf(fmaxf(x2v + g_c2[bn + c4 + 2] - 2.0f * v.z, 0.0f));
            v.w = sqrtf(fmaxf(x2v + g_c2[bn + c4 + 3] - 2.0f * v.w, 0.0f));
        }
        *(float4*)(out + (size_t)(bm + row) * LDO + bn + c4) = v;
    }
}

// ───────── softmax(-alpha*d) → fp32 out + bf16 hi/lo scratch ─────────
__global__ void softmax_kernel(const float* __restrict__ dist, float* __restrict__ soft) {
    __shared__ float sm[32];
    size_t row = blockIdx.x;
    int t = threadIdx.x;
    float4 v = ((const float4*)(dist + row * Kk))[t];
    float m = block_reduce(fminf(fminf(v.x, v.y), fminf(v.z, v.w)), sm, 1);
    float4 e;
    e.x = expf(-ALPHA * (v.x - m));
    e.y = expf(-ALPHA * (v.y - m));
    e.z = expf(-ALPHA * (v.z - m));
    e.w = expf(-ALPHA * (v.w - m));
    float s = block_reduce(e.x + e.y + e.z + e.w, sm, 0);
    float inv = 1.0f / s;
    e.x *= inv; e.y *= inv; e.z *= inv; e.w *= inv;
    ((float4*)(soft + row * Kk))[t] = e;
    uint2 h, l;
    split4(e, h, l);
    ((uint2*)(g_sa_hi + row * Kk))[t] = h;
    ((uint2*)(g_sa_lo + row * Kk))[t] = l;
}

// ───────── launch ─────────
extern "C" void kernel_launch(void* const* d_in, const int* in_sizes, int n_in,
                              void* d_out, int out_size) {
    const float* x = (const float*)d_in[0];
    const float* w = (const float*)d_in[1];
    const float* b = (const float*)d_in[2];
    const float* C = (const float*)d_in[3];

    float* out  = (float*)d_out;
    float* dist = out;
    float* soft = out + (size_t)Nn * Kk;
    float* rec  = out + 2 * (size_t)Nn * Kk;

    cudaFuncSetAttribute(mma_gemm<0>, cudaFuncAttributeMaxDynamicSharedMemorySize, DSMEM);
    cudaFuncSetAttribute(mma_gemm<1>, cudaFuncAttributeMaxDynamicSharedMemorySize, DSMEM);

    ln_kernel<<<Nn, 128>>>(x, w, b);
    c2_kernel<<<Kk, 128>>>(C);
    transpose_c<<<dim3(Dd / 32, Kk / 32), dim3(32, 8)>>>(C);

    mma_gemm<0><<<dim3(Kk / BN, Nn / BM), 256, DSMEM>>>(dist);
    softmax_kernel<<<Nn, 256>>>(dist, soft);
    mma_gemm<1><<<dim3(Dd / BN, Nn / BM), 256, DSMEM>>>(rec);
}

// round 14
// speedup vs baseline: 1.0131x; 1.0131x over previous
#include <cuda_runtime.h>
#include <cuda_bf16.h>
#include <cstdint>
#include <math.h>

#define Nn 131072
#define Dd 512
#define Kk 1024
#define ALPHA 32.0f
#define EPS 1e-5f

// GEMM tiling: CTA 128x256 (512 threads), warp tile 64x32 (2x8 warps)
#define BM 128
#define BN 256
#define KC 32                  // K elems per chunk
#define LDSB 80                // smem row stride bytes (64 data + 16 pad)
#define PLANE_A (128 * LDSB)   // 10240 B
#define PLANE_B (256 * LDSB)   // 20480 B
#define OFF_AHI 0
#define OFF_ALO PLANE_A
#define OFF_BHI (2 * PLANE_A)
#define OFF_BLO (2 * PLANE_A + PLANE_B)
#define SSTAGE (2 * PLANE_A + 2 * PLANE_B)   // 61440 B
#define NSTAGE 2
#define EPI_LD 132             // epilogue f32 row stride (528 B), used per 128-col half
#define DSMEM (NSTAGE * SSTAGE)   // 122880 B

// Scratch (only referenced from DEVICE code)
__device__ float g_x2[Nn];
__device__ float g_c2[Kk];
__device__ __nv_bfloat16 g_xa_hi[(size_t)Nn * Dd];   // xn hi/lo (N x D)
__device__ __nv_bfloat16 g_xa_lo[(size_t)Nn * Dd];
__device__ __nv_bfloat16 g_cb_hi[(size_t)Kk * Dd];   // C hi/lo (K x D)
__device__ __nv_bfloat16 g_cb_lo[(size_t)Kk * Dd];
__device__ __nv_bfloat16 g_ct_hi[(size_t)Dd * Kk];   // C^T hi/lo (D x K)
__device__ __nv_bfloat16 g_ct_lo[(size_t)Dd * Kk];
__device__ __nv_bfloat16 g_sa_hi[(size_t)Nn * Kk];   // soft hi/lo (N x K)
__device__ __nv_bfloat16 g_sa_lo[(size_t)Nn * Kk];

// ───────── helpers ─────────
__device__ __forceinline__ uint32_t smem_u32(const void* p) {
    uint32_t a;
    asm("{ .reg .u64 t; cvta.to.shared.u64 t, %1; cvt.u32.u64 %0, t; }" : "=r"(a) : "l"(p));
    return a;
}
#define CP_ASYNC16(dst, src) \
    asm volatile("cp.async.cg.shared.global [%0], [%1], 16;" :: "r"(dst), "l"(src))
#define CP_COMMIT() asm volatile("cp.async.commit_group;" ::: "memory")
#define CP_WAIT(n)  asm volatile("cp.async.wait_group %0;" :: "n"(n) : "memory")

__device__ __forceinline__ void mma16816(float* c, uint32_t a0, uint32_t a1, uint32_t a2,
                                         uint32_t a3, uint32_t b0, uint32_t b1) {
    asm volatile("mma.sync.aligned.m16n8k16.row.col.f32.bf16.bf16.f32 "
                 "{%0,%1,%2,%3}, {%4,%5,%6,%7}, {%8,%9}, {%0,%1,%2,%3};"
                 : "+f"(c[0]), "+f"(c[1]), "+f"(c[2]), "+f"(c[3])
                 : "r"(a0), "r"(a1), "r"(a2), "r"(a3), "r"(b0), "r"(b1));
}
// bf16 hi/lo split of 4 floats
__device__ __forceinline__ void split4(float4 v, uint2& h, uint2& l) {
    __nv_bfloat16 h0 = __float2bfloat16(v.x), h1 = __float2bfloat16(v.y);
    __nv_bfloat16 h2 = __float2bfloat16(v.z), h3 = __float2bfloat16(v.w);
    __nv_bfloat16 l0 = __float2bfloat16(v.x - __bfloat162float(h0));
    __nv_bfloat16 l1 = __float2bfloat16(v.y - __bfloat162float(h1));
    __nv_bfloat16 l2 = __float2bfloat16(v.z - __bfloat162float(h2));
    __nv_bfloat16 l3 = __float2bfloat16(v.w - __bfloat162float(h3));
    __nv_bfloat162 a = __halves2bfloat162(h0, h1), b = __halves2bfloat162(h2, h3);
    __nv_bfloat162 c = __halves2bfloat162(l0, l1), d = __halves2bfloat162(l2, l3);
    h.x = *(uint32_t*)&a; h.y = *(uint32_t*)&b;
    l.x = *(uint32_t*)&c; l.y = *(uint32_t*)&d;
}

__device__ __forceinline__ float block_reduce(float v, float* sm, int op) {
    int lane = threadIdx.x & 31, wid = threadIdx.x >> 5;
    #pragma unroll
    for (int o = 16; o; o >>= 1) {
        float t = __shfl_xor_sync(0xffffffffu, v, o);
        v = op ? fminf(v, t) : (v + t);
    }
    if (lane == 0) sm[wid] = v;
    __syncthreads();
    int nw = blockDim.x >> 5;
    if (wid == 0) {
        float r = (lane < nw) ? sm[lane] : (op ? 3.4e38f : 0.0f);
        #pragma unroll
        for (int o = 16; o; o >>= 1) {
            float t = __shfl_xor_sync(0xffffffffu, r, o);
            r = op ? fminf(r, t) : (r + t);
        }
        if (lane == 0) sm[0] = r;
    }
    __syncthreads();
    float r = sm[0];
    __syncthreads();
    return r;
}

// ───────── layernorm → bf16 hi/lo + ||xn||² ─────────
__global__ void ln_kernel(const float* __restrict__ x, const float* __restrict__ w,
                          const float* __restrict__ b) {
    __shared__ float sm[32];
    size_t row = blockIdx.x;
    int t = threadIdx.x;
    float4 v = ((const float4*)(x + row * Dd))[t];
    float s = block_reduce(v.x + v.y + v.z + v.w, sm, 0);
    float mean = s * (1.0f / Dd);
    float d0 = v.x - mean, d1 = v.y - mean, d2 = v.z - mean, d3 = v.w - mean;
    float sq = block_reduce(d0 * d0 + d1 * d1 + d2 * d2 + d3 * d3, sm, 0);
    float inv = 1.0f / (sqrtf(sq * (1.0f / Dd)) + EPS);
    float4 wv = ((const float4*)w)[t];
    float4 bv = ((const float4*)b)[t];
    float4 o;
    o.x = d0 * inv * wv.x + bv.x;  o.y = d1 * inv * wv.y + bv.y;
    o.z = d2 * inv * wv.z + bv.z;  o.w = d3 * inv * wv.w + bv.w;
    float n2 = block_reduce(o.x * o.x + o.y * o.y + o.z * o.z + o.w * o.w, sm, 0);
    if (t == 0) g_x2[row] = n2;
    uint2 h, l;
    split4(o, h, l);
    ((uint2*)(g_xa_hi + row * Dd))[t] = h;
    ((uint2*)(g_xa_lo + row * Dd))[t] = l;
}

// ───────── center norms + C hi/lo ─────────
__global__ void c2_kernel(const float* __restrict__ C) {
    __shared__ float sm[32];
    size_t row = blockIdx.x;
    int t = threadIdx.x;
    float4 v = ((const float4*)(C + row * Dd))[t];
    float s = block_reduce(v.x * v.x + v.y * v.y + v.z * v.z + v.w * v.w, sm, 0);
    if (t == 0) g_c2[row] = s;
    uint2 h, l;
    split4(v, h, l);
    ((uint2*)(g_cb_hi + row * Dd))[t] = h;
    ((uint2*)(g_cb_lo + row * Dd))[t] = l;
}

// ───────── transpose C → C^T hi/lo (D x K) ─────────
__global__ void transpose_c(const float* __restrict__ C) {
    __shared__ float t[32][33];
    int x = blockIdx.x * 32 + threadIdx.x;   // d
    int y = blockIdx.y * 32 + threadIdx.y;   // k
    #pragma unroll
    for (int j = 0; j < 4; j++)
        t[threadIdx.y + j * 8][threadIdx.x] = C[(size_t)(y + j * 8) * Dd + x];
    __syncthreads();
    int x2 = blockIdx.y * 32 + threadIdx.x;  // k
    int y2 = blockIdx.x * 32 + threadIdx.y;  // d
    #pragma unroll
    for (int j = 0; j < 4; j++) {
        float v = t[threadIdx.x][threadIdx.y + j * 8];
        __nv_bfloat16 hi = __float2bfloat16(v);
        __nv_bfloat16 lo = __float2bfloat16(v - __bfloat162float(hi));
        g_ct_hi[(size_t)(y2 + j * 8) * Kk + x2] = hi;
        g_ct_lo[(size_t)(y2 + j * 8) * Kk + x2] = lo;
    }
}

// ───────── HMMA bf16x3 GEMM: 512 threads, CTA 128x256, warp 64x32 ─────────
// MODE 0 (dist): A = g_xa (N x D), B = g_cb (K x D), KTOT=512, sqrt epilogue, ldo=Kk
// MODE 1 (rec):  A = g_sa (N x K), B = g_ct (D x K), KTOT=1024, identity, ldo=Dd
template <int MODE>
__global__ void __launch_bounds__(512, 1)
mma_gemm(float* __restrict__ out) {
    constexpr int KTOT = (MODE == 0) ? Dd : Kk;
    constexpr int LDAB = (MODE == 0) ? Dd : Kk;
    constexpr int LDO  = (MODE == 0) ? Kk : Dd;
    const __nv_bfloat16* Ah = (MODE == 0) ? g_xa_hi : g_sa_hi;
    const __nv_bfloat16* Al = (MODE == 0) ? g_xa_lo : g_sa_lo;
    const __nv_bfloat16* Bh = (MODE == 0) ? g_cb_hi : g_ct_hi;
    const __nv_bfloat16* Bl = (MODE == 0) ? g_cb_lo : g_ct_lo;

    extern __shared__ char smc[];
    const uint32_t sbase = smem_u32(smc);
    const int tid = threadIdx.x;
    const int wid = tid >> 5, lane = tid & 31;
    const int g = lane >> 2, tig = lane & 3;
    const int wm = wid & 1, wn = wid >> 1;       // warp tile 64x32, wn in 0..7
    const int bm = blockIdx.y * BM;
    const int bn = blockIdx.x * BN;
    constexpr int NC = KTOT / KC;

    float acc[4][4][4];
    #pragma unroll
    for (int i = 0; i < 4; i++)
        #pragma unroll
        for (int j = 0; j < 4; j++)
            #pragma unroll
            for (int q = 0; q < 4; q++) acc[i][j][q] = 0.0f;

    // cp.async: 6 x 16B per thread; 3072 chunks = A(2x128x4) + B(2x256x4)
    auto prefetch = [&](int c) {
        uint32_t sb = sbase + (uint32_t)(c & 1) * SSTAGE;
        int kc = c * KC;
        #pragma unroll
        for (int i = 0; i < 6; i++) {
            int idx = tid + i * 512;                 // 0..3071
            int rg = idx >> 2, seg = idx & 3;        // row-group 0..767
            const __nv_bfloat16* src;
            uint32_t dst;
            if (rg < 256) {                          // A planes: 128 hi + 128 lo
                int pl = rg >> 7, row = rg & 127;
                dst = sb + (pl ? OFF_ALO : OFF_AHI) + (uint32_t)row * LDSB + seg * 16;
                src = (pl ? Al : Ah) + (size_t)(bm + row) * LDAB + kc + seg * 8;
            } else {                                 // B planes: 256 hi + 256 lo
                int rb = rg - 256;
                int pl = rb >> 8, row = rb & 255;
                dst = sb + (pl ? OFF_BLO : OFF_BHI) + (uint32_t)row * LDSB + seg * 16;
                src = (pl ? Bl : Bh) + (size_t)(bn + row) * LDAB + kc + seg * 8;
            }
            CP_ASYNC16(dst, src);
        }
        CP_COMMIT();
    };

    prefetch(0);

    for (int c = 0; c < NC; c++) {
        CP_WAIT(0);               // stage c resident
        __syncthreads();
        if (c + 1 < NC) prefetch(c + 1);   // overlaps compute c

        const char* stp = smc + (c & 1) * SSTAGE;
        #pragma unroll
        for (int ks = 0; ks < 2; ks++) {
            // B fragments resident for this ks (16 regs)
            uint32_t bh[4][2], bl[4][2];
            #pragma unroll
            for (int fn = 0; fn < 4; fn++) {
                const char* br = stp + OFF_BHI + (wn * 32 + fn * 8 + g) * LDSB + ks * 32 + tig * 4;
                bh[fn][0] = *(const uint32_t*)(br);
                bh[fn][1] = *(const uint32_t*)(br + 16);
                bl[fn][0] = *(const uint32_t*)(br + PLANE_B);
                bl[fn][1] = *(const uint32_t*)(br + PLANE_B + 16);
            }
            // fm pairs; 3 compensation passes pass-outer (8 independent accs/pass)
            #pragma unroll
            for (int fp = 0; fp < 2; fp++) {
                uint32_t ah[2][4], al[2][4];
                #pragma unroll
                for (int f = 0; f < 2; f++) {
                    int fm = fp * 2 + f;
                    const char* ar = stp + OFF_AHI + (wm * 64 + fm * 16 + g) * LDSB + ks * 32 + tig * 4;
                    ah[f][0] = *(const uint32_t*)(ar);
                    ah[f][1] = *(const uint32_t*)(ar + 8 * LDSB);
                    ah[f][2] = *(const uint32_t*)(ar + 16);
                    ah[f][3] = *(const uint32_t*)(ar + 8 * LDSB + 16);
                    al[f][0] = *(const uint32_t*)(ar + PLANE_A);
                    al[f][1] = *(const uint32_t*)(ar + PLANE_A + 8 * LDSB);
                    al[f][2] = *(const uint32_t*)(ar + PLANE_A + 16);
                    al[f][3] = *(const uint32_t*)(ar + PLANE_A + 8 * LDSB + 16);
                }
                #pragma unroll
                for (int f = 0; f < 2; f++)
                    #pragma unroll
                    for (int fn = 0; fn < 4; fn++)
                        mma16816(acc[fp * 2 + f][fn], ah[f][0], ah[f][1], ah[f][2], ah[f][3],
                                 bh[fn][0], bh[fn][1]);
                #pragma unroll
                for (int f = 0; f < 2; f++)
                    #pragma unroll
                    for (int fn = 0; fn < 4; fn++)
                        mma16816(acc[fp * 2 + f][fn], ah[f][0], ah[f][1], ah[f][2], ah[f][3],
                                 bl[fn][0], bl[fn][1]);
                #pragma unroll
                for (int f = 0; f < 2; f++)
                    #pragma unroll
                    for (int fn = 0; fn < 4; fn++)
                        mma16816(acc[fp * 2 + f][fn], al[f][0], al[f][1], al[f][2], al[f][3],
                                 bh[fn][0], bh[fn][1]);
            }
        }
    }

    __syncthreads();   // all warps done before smem reuse

    // epilogue in two 128-column halves (smem 128 x EPI_LD f32 = 67.6 KB)
    float* epi = (float*)smc;
    #pragma unroll
    for (int h = 0; h < 2; h++) {
        if ((wn >> 2) == h) {
            int cwbase = (wn & 3) * 32;
            #pragma unroll
            for (int fm = 0; fm < 4; fm++) {
                int r0 = wm * 64 + fm * 16 + g;
                #pragma unroll
                for (int fn = 0; fn < 4; fn++) {
                    int cc = cwbase + fn * 8 + 2 * tig;
                    *(float2*)&epi[r0 * EPI_LD + cc]       = make_float2(acc[fm][fn][0], acc[fm][fn][1]);
                    *(float2*)&epi[(r0 + 8) * EPI_LD + cc] = make_float2(acc[fm][fn][2], acc[fm][fn][3]);
                }
            }
        }
        __syncthreads();
        #pragma unroll
        for (int i = 0; i < 8; i++) {
            int idx = tid + i * 512;
            int row = idx >> 5, c4 = (idx & 31) * 4;
            float4 v = *(float4*)&epi[row * EPI_LD + c4];
            int ocol = bn + h * 128 + c4;
            if (MODE == 0) {
                float x2v = g_x2[bm + row];
                v.x = sqrtf(fmaxf(x2v + g_c2[ocol + 0] - 2.0f * v.x, 0.0f));
                v.y = sqrtf(fmaxf(x2v + g_c2[ocol + 1] - 2.0f * v.y, 0.0f));
                v.z = sqrtf(fmaxf(x2v + g_c2[ocol + 2] - 2.0f * v.z, 0.0f));
                v.w = sqrtf(fmaxf(x2v + g_c2[ocol + 3] - 2.0f * v.w, 0.0f));
            }
            *(float4*)(out + (size_t)(bm + row) * LDO + ocol) = v;
        }
        __syncthreads();
    }
}

// ───────── softmax(-alpha*d) → fp32 out + bf16 hi/lo scratch ─────────
__global__ void softmax_kernel(const float* __restrict__ dist, float* __restrict__ soft) {
    __shared__ float sm[32];
    size_t row = blockIdx.x;
    int t = threadIdx.x;
    float4 v = ((const float4*)(dist + row * Kk))[t];
    float m = block_reduce(fminf(fminf(v.x, v.y), fminf(v.z, v.w)), sm, 1);
    float4 e;
    e.x = expf(-ALPHA * (v.x - m));
    e.y = expf(-ALPHA * (v.y - m));
    e.z = expf(-ALPHA * (v.z - m));
    e.w = expf(-ALPHA * (v.w - m));
    float s = block_reduce(e.x + e.y + e.z + e.w, sm, 0);
    float inv = 1.0f / s;
    e.x *= inv; e.y *= inv; e.z *= inv; e.w *= inv;
    ((float4*)(soft + row * Kk))[t] = e;
    uint2 h, l;
    split4(e, h, l);
    ((uint2*)(g_sa_hi + row * Kk))[t] = h;
    ((uint2*)(g_sa_lo + row * Kk))[t] = l;
}

// ───────── launch ─────────
extern "C" void kernel_launch(void* const* d_in, const int* in_sizes, int n_in,
                              void* d_out, int out_size) {
    const float* x = (const float*)d_in[0];
    const float* w = (const float*)d_in[1];
    const float* b = (const float*)d_in[2];
    const float* C = (const float*)d_in[3];

    float* out  = (float*)d_out;
    float* dist = out;
    float* soft = out + (size_t)Nn * Kk;
    float* rec  = out + 2 * (size_t)Nn * Kk;

    cudaFuncSetAttribute(mma_gemm<0>, cudaFuncAttributeMaxDynamicSharedMemorySize, DSMEM);
    cudaFuncSetAttribute(mma_gemm<1>, cudaFuncAttributeMaxDynamicSharedMemorySize, DSMEM);

    ln_kernel<<<Nn, 128>>>(x, w, b);
    c2_kernel<<<Kk, 128>>>(C);
    transpose_c<<<dim3(Dd / 32, Kk / 32), dim3(32, 8)>>>(C);

    mma_gemm<0><<<dim3(Kk / BN, Nn / BM), 512, DSMEM>>>(dist);
    softmax_kernel<<<Nn, 256>>>(dist, soft);
    mma_gemm<1><<<dim3(Dd / BN, Nn / BM), 512, DSMEM>>>(rec);
}

// round 16
// speedup vs baseline: 1.5170x; 1.4973x over previous
#include <cuda_runtime.h>
#include <cuda_bf16.h>
#include <cuda_fp16.h>
#include <cstdint>
#include <math.h>

#define Nn 131072
#define Dd 512
#define Kk 1024
#define ALPHA 32.0f
#define EPS 1e-5f

// Common tiling
#define BM 128
#define BN 128
#define KC 32
#define LDSB 80                 // smem row stride bytes (64 data + 16 pad)
#define PLANE (128 * LDSB)      // 10240 B: 128 rows x 32 elem (2B) plane
#define EPI_LD 132              // epilogue f32 row stride (528 B, 16B-aligned)

// dist: 4 planes (Ahi,Alo,Bhi,Blo), 2 stages
#define SSTAGE_D (4 * PLANE)    // 40960
#define DSMEM_D (2 * SSTAGE_D)  // 81920
// rec: 2 planes (A,B) fp16, 4 stages
#define SSTAGE_R (2 * PLANE)    // 20480
#define NSTAGE_R 4
#define DSMEM_R (NSTAGE_R * SSTAGE_R)  // 81920 (covers epi 128x132x4=67584)

// Scratch (only referenced from DEVICE code)
__device__ float g_x2[Nn];
__device__ float g_c2[Kk];
__device__ __nv_bfloat16 g_xa_hi[(size_t)Nn * Dd];   // xn hi/lo (N x D)
__device__ __nv_bfloat16 g_xa_lo[(size_t)Nn * Dd];
__device__ __nv_bfloat16 g_cb_hi[(size_t)Kk * Dd];   // C hi/lo (K x D)
__device__ __nv_bfloat16 g_cb_lo[(size_t)Kk * Dd];
__device__ __half g_ct_h[(size_t)Dd * Kk];           // C^T fp16 (D x K)
__device__ __half g_sa_h[(size_t)Nn * Kk];           // soft fp16 (N x K)

// ───────── helpers ─────────
__device__ __forceinline__ uint32_t smem_u32(const void* p) {
    uint32_t a;
    asm("{ .reg .u64 t; cvta.to.shared.u64 t, %1; cvt.u32.u64 %0, t; }" : "=r"(a) : "l"(p));
    return a;
}
#define CP_ASYNC16(dst, src) \
    asm volatile("cp.async.cg.shared.global [%0], [%1], 16;" :: "r"(dst), "l"(src))
#define CP_COMMIT() asm volatile("cp.async.commit_group;" ::: "memory")
#define CP_WAIT(n)  asm volatile("cp.async.wait_group %0;" :: "n"(n) : "memory")

__device__ __forceinline__ void ldsm4(uint32_t& r0, uint32_t& r1, uint32_t& r2, uint32_t& r3,
                                      uint32_t addr) {
    asm volatile("ldmatrix.sync.aligned.m8n8.x4.shared.b16 {%0,%1,%2,%3}, [%4];"
                 : "=r"(r0), "=r"(r1), "=r"(r2), "=r"(r3) : "r"(addr));
}
__device__ __forceinline__ void mma_bf16(float* c, uint32_t a0, uint32_t a1, uint32_t a2,
                                         uint32_t a3, uint32_t b0, uint32_t b1) {
    asm volatile("mma.sync.aligned.m16n8k16.row.col.f32.bf16.bf16.f32 "
                 "{%0,%1,%2,%3}, {%4,%5,%6,%7}, {%8,%9}, {%0,%1,%2,%3};"
                 : "+f"(c[0]), "+f"(c[1]), "+f"(c[2]), "+f"(c[3])
                 : "r"(a0), "r"(a1), "r"(a2), "r"(a3), "r"(b0), "r"(b1));
}
__device__ __forceinline__ void mma_f16(float* c, uint32_t a0, uint32_t a1, uint32_t a2,
                                        uint32_t a3, uint32_t b0, uint32_t b1) {
    asm volatile("mma.sync.aligned.m16n8k16.row.col.f32.f16.f16.f32 "
                 "{%0,%1,%2,%3}, {%4,%5,%6,%7}, {%8,%9}, {%0,%1,%2,%3};"
                 : "+f"(c[0]), "+f"(c[1]), "+f"(c[2]), "+f"(c[3])
                 : "r"(a0), "r"(a1), "r"(a2), "r"(a3), "r"(b0), "r"(b1));
}
// bf16 hi/lo split of 4 floats
__device__ __forceinline__ void split4(float4 v, uint2& h, uint2& l) {
    __nv_bfloat16 h0 = __float2bfloat16(v.x), h1 = __float2bfloat16(v.y);
    __nv_bfloat16 h2 = __float2bfloat16(v.z), h3 = __float2bfloat16(v.w);
    __nv_bfloat16 l0 = __float2bfloat16(v.x - __bfloat162float(h0));
    __nv_bfloat16 l1 = __float2bfloat16(v.y - __bfloat162float(h1));
    __nv_bfloat16 l2 = __float2bfloat16(v.z - __bfloat162float(h2));
    __nv_bfloat16 l3 = __float2bfloat16(v.w - __bfloat162float(h3));
    __nv_bfloat162 a = __halves2bfloat162(h0, h1), b = __halves2bfloat162(h2, h3);
    __nv_bfloat162 c = __halves2bfloat162(l0, l1), d = __halves2bfloat162(l2, l3);
    h.x = *(uint32_t*)&a; h.y = *(uint32_t*)&b;
    l.x = *(uint32_t*)&c; l.y = *(uint32_t*)&d;
}

__device__ __forceinline__ float block_reduce(float v, float* sm, int op) {
    int lane = threadIdx.x & 31, wid = threadIdx.x >> 5;
    #pragma unroll
    for (int o = 16; o; o >>= 1) {
        float t = __shfl_xor_sync(0xffffffffu, v, o);
        v = op ? fminf(v, t) : (v + t);
    }
    if (lane == 0) sm[wid] = v;
    __syncthreads();
    int nw = blockDim.x >> 5;
    if (wid == 0) {
        float r = (lane < nw) ? sm[lane] : (op ? 3.4e38f : 0.0f);
        #pragma unroll
        for (int o = 16; o; o >>= 1) {
            float t = __shfl_xor_sync(0xffffffffu, r, o);
            r = op ? fminf(r, t) : (r + t);
        }
        if (lane == 0) sm[0] = r;
    }
    __syncthreads();
    float r = sm[0];
    __syncthreads();
    return r;
}

// ───────── layernorm → bf16 hi/lo + ||xn||² ─────────
__global__ void ln_kernel(const float* __restrict__ x, const float* __restrict__ w,
                          const float* __restrict__ b) {
    __shared__ float sm[32];
    size_t row = blockIdx.x;
    int t = threadIdx.x;
    float4 v = ((const float4*)(x + row * Dd))[t];
    float s = block_reduce(v.x + v.y + v.z + v.w, sm, 0);
    float mean = s * (1.0f / Dd);
    float d0 = v.x - mean, d1 = v.y - mean, d2 = v.z - mean, d3 = v.w - mean;
    float sq = block_reduce(d0 * d0 + d1 * d1 + d2 * d2 + d3 * d3, sm, 0);
    float inv = 1.0f / (sqrtf(sq * (1.0f / Dd)) + EPS);
    float4 wv = ((const float4*)w)[t];
    float4 bv = ((const float4*)b)[t];
    float4 o;
    o.x = d0 * inv * wv.x + bv.x;  o.y = d1 * inv * wv.y + bv.y;
    o.z = d2 * inv * wv.z + bv.z;  o.w = d3 * inv * wv.w + bv.w;
    float n2 = block_reduce(o.x * o.x + o.y * o.y + o.z * o.z + o.w * o.w, sm, 0);
    if (t == 0) g_x2[row] = n2;
    uint2 h, l;
    split4(o, h, l);
    ((uint2*)(g_xa_hi + row * Dd))[t] = h;
    ((uint2*)(g_xa_lo + row * Dd))[t] = l;
}

// ───────── center norms + C hi/lo ─────────
__global__ void c2_kernel(const float* __restrict__ C) {
    __shared__ float sm[32];
    size_t row = blockIdx.x;
    int t = threadIdx.x;
    float4 v = ((const float4*)(C + row * Dd))[t];
    float s = block_reduce(v.x * v.x + v.y * v.y + v.z * v.z + v.w * v.w, sm, 0);
    if (t == 0) g_c2[row] = s;
    uint2 h, l;
    split4(v, h, l);
    ((uint2*)(g_cb_hi + row * Dd))[t] = h;
    ((uint2*)(g_cb_lo + row * Dd))[t] = l;
}

// ───────── transpose C → C^T fp16 (D x K) ─────────
__global__ void transpose_c(const float* __restrict__ C) {
    __shared__ float t[32][33];
    int x = blockIdx.x * 32 + threadIdx.x;   // d
    int y = blockIdx.y * 32 + threadIdx.y;   // k
    #pragma unroll
    for (int j = 0; j < 4; j++)
        t[threadIdx.y + j * 8][threadIdx.x] = C[(size_t)(y + j * 8) * Dd + x];
    __syncthreads();
    int x2 = blockIdx.y * 32 + threadIdx.x;  // k
    int y2 = blockIdx.x * 32 + threadIdx.y;  // d
    #pragma unroll
    for (int j = 0; j < 4; j++)
        g_ct_h[(size_t)(y2 + j * 8) * Kk + x2] = __float2half(t[threadIdx.x][threadIdx.y + j * 8]);
}

// ───────── dist GEMM: bf16x3, ldmatrix fragments, 2-stage cp.async, 2 CTAs/SM ─────────
__global__ void __launch_bounds__(256, 2)
dist_gemm(float* __restrict__ out) {
    const __nv_bfloat16* Ah = g_xa_hi;
    const __nv_bfloat16* Al = g_xa_lo;
    const __nv_bfloat16* Bh = g_cb_hi;
    const __nv_bfloat16* Bl = g_cb_lo;

    extern __shared__ char smc[];
    const uint32_t sbase = smem_u32(smc);
    const int tid = threadIdx.x;
    const int wid = tid >> 5, lane = tid & 31;
    const int g = lane >> 2, tig = lane & 3;
    const int wm = wid & 1, wn = wid >> 1;
    const int bm = blockIdx.y * BM;
    const int bn = blockIdx.x * BN;
    constexpr int NC = Dd / KC;

    // ldmatrix lane offsets (validated: R5 == R6 bit-identical)
    const uint32_t a_off = (uint32_t)(lane & 15) * LDSB + (uint32_t)(lane >> 4) * 16;
    const int bmat = lane >> 3, brow = lane & 7;
    const uint32_t b_off = (uint32_t)((bmat >> 1) * 8 + brow) * LDSB + (uint32_t)(bmat & 1) * 16;

    float acc[4][4][4];
    #pragma unroll
    for (int i = 0; i < 4; i++)
        #pragma unroll
        for (int j = 0; j < 4; j++)
            #pragma unroll
            for (int q = 0; q < 4; q++) acc[i][j][q] = 0.0f;

    auto prefetch = [&](int c) {
        uint32_t sb = sbase + (uint32_t)(c & 1) * SSTAGE_D;
        int kc = c * KC;
        #pragma unroll
        for (int i = 0; i < 8; i++) {
            int idx = tid + i * 256;
            int pl = idx >> 9, r = idx & 511;
            int row = r >> 2, seg = r & 3;
            uint32_t dst = sb + (uint32_t)pl * PLANE + (uint32_t)row * LDSB + seg * 16;
            const __nv_bfloat16* src;
            if (pl == 0)      src = Ah + (size_t)(bm + row) * Dd + kc + seg * 8;
            else if (pl == 1) src = Al + (size_t)(bm + row) * Dd + kc + seg * 8;
            else if (pl == 2) src = Bh + (size_t)(bn + row) * Dd + kc + seg * 8;
            else              src = Bl + (size_t)(bn + row) * Dd + kc + seg * 8;
            CP_ASYNC16(dst, src);
        }
        CP_COMMIT();
    };

    prefetch(0);

    for (int c = 0; c < NC; c++) {
        CP_WAIT(0);
        __syncthreads();
        if (c + 1 < NC) prefetch(c + 1);

        const uint32_t stg = sbase + (uint32_t)(c & 1) * SSTAGE_D;
        #pragma unroll
        for (int ks = 0; ks < 2; ks++) {
            uint32_t bh[4][2], bl[4][2];
            #pragma unroll
            for (int p = 0; p < 2; p++) {
                uint32_t r = stg + 2 * PLANE + (uint32_t)(wn * 32 + p * 16) * LDSB + ks * 32 + b_off;
                ldsm4(bh[p * 2][0], bh[p * 2][1], bh[p * 2 + 1][0], bh[p * 2 + 1][1], r);
                ldsm4(bl[p * 2][0], bl[p * 2][1], bl[p * 2 + 1][0], bl[p * 2 + 1][1], r + PLANE);
            }
            #pragma unroll
            for (int fp = 0; fp < 2; fp++) {
                uint32_t ah[2][4], al[2][4];
                #pragma unroll
                for (int f = 0; f < 2; f++) {
                    int fm = fp * 2 + f;
                    uint32_t r = stg + (uint32_t)(wm * 64 + fm * 16) * LDSB + ks * 32 + a_off;
                    ldsm4(ah[f][0], ah[f][1], ah[f][2], ah[f][3], r);
                    ldsm4(al[f][0], al[f][1], al[f][2], al[f][3], r + PLANE);
                }
                #pragma unroll
                for (int f = 0; f < 2; f++)
                    #pragma unroll
                    for (int fn = 0; fn < 4; fn++)
                        mma_bf16(acc[fp * 2 + f][fn], ah[f][0], ah[f][1], ah[f][2], ah[f][3],
                                 bh[fn][0], bh[fn][1]);
                #pragma unroll
                for (int f = 0; f < 2; f++)
                    #pragma unroll
                    for (int fn = 0; fn < 4; fn++)
                        mma_bf16(acc[fp * 2 + f][fn], ah[f][0], ah[f][1], ah[f][2], ah[f][3],
                                 bl[fn][0], bl[fn][1]);
                #pragma unroll
                for (int f = 0; f < 2; f++)
                    #pragma unroll
                    for (int fn = 0; fn < 4; fn++)
                        mma_bf16(acc[fp * 2 + f][fn], al[f][0], al[f][1], al[f][2], al[f][3],
                                 bh[fn][0], bh[fn][1]);
            }
        }
    }

    __syncthreads();

    float* epi = (float*)smc;
    #pragma unroll
    for (int fm = 0; fm < 4; fm++) {
        int r0 = wm * 64 + fm * 16 + g;
        #pragma unroll
        for (int fn = 0; fn < 4; fn++) {
            int cc = wn * 32 + fn * 8 + 2 * tig;
            *(float2*)&epi[r0 * EPI_LD + cc]       = make_float2(acc[fm][fn][0], acc[fm][fn][1]);
            *(float2*)&epi[(r0 + 8) * EPI_LD + cc] = make_float2(acc[fm][fn][2], acc[fm][fn][3]);
        }
    }
    __syncthreads();
    #pragma unroll
    for (int i = 0; i < 16; i++) {
        int idx = tid + i * 256;
        int row = idx >> 5, c4 = (idx & 31) * 4;
        float4 v = *(float4*)&epi[row * EPI_LD + c4];
        float x2v = g_x2[bm + row];
        v.x = sqrtf(fmaxf(x2v + g_c2[bn + c4 + 0] - 2.0f * v.x, 0.0f));
        v.y = sqrtf(fmaxf(x2v + g_c2[bn + c4 + 1] - 2.0f * v.y, 0.0f));
        v.z = sqrtf(fmaxf(x2v + g_c2[bn + c4 + 2] - 2.0f * v.z, 0.0f));
        v.w = sqrtf(fmaxf(x2v + g_c2[bn + c4 + 3] - 2.0f * v.w, 0.0f));
        *(float4*)(out + (size_t)(bm + row) * Kk + bn + c4) = v;
    }
}

// ───────── rec GEMM: fp16 single pass, ldmatrix, 4-stage cp.async, 2 CTAs/SM ─────────
__global__ void __launch_bounds__(256, 2)
rec_gemm(float* __restrict__ out) {
    extern __shared__ char smc[];
    const uint32_t sbase = smem_u32(smc);
    const int tid = threadIdx.x;
    const int wid = tid >> 5, lane = tid & 31;
    const int g = lane >> 2, tig = lane & 3;
    const int wm = wid & 1, wn = wid >> 1;
    const int bm = blockIdx.y * BM;
    const int bn = blockIdx.x * BN;
    constexpr int NC = Kk / KC;   // 32

    const uint32_t a_off = (uint32_t)(lane & 15) * LDSB + (uint32_t)(lane >> 4) * 16;
    const int bmat = lane >> 3, brow = lane & 7;
    const uint32_t b_off = (uint32_t)((bmat >> 1) * 8 + brow) * LDSB + (uint32_t)(bmat & 1) * 16;

    float acc[4][4][4];
    #pragma unroll
    for (int i = 0; i < 4; i++)
        #pragma unroll
        for (int j = 0; j < 4; j++)
            #pragma unroll
            for (int q = 0; q < 4; q++) acc[i][j][q] = 0.0f;

    // 1024 x 16B chunks per stage: A (128 rows x 4) + B (128 rows x 4)
    auto prefetch = [&](int c) {
        uint32_t sb = sbase + (uint32_t)(c % NSTAGE_R) * SSTAGE_R;
        int kc = c * KC;
        #pragma unroll
        for (int i = 0; i < 4; i++) {
            int idx = tid + i * 256;
            int rg = idx >> 2, seg = idx & 3;
            const __half* src;
            uint32_t dst;
            if (rg < 128) {
                dst = sb + (uint32_t)rg * LDSB + seg * 16;
                src = g_sa_h + (size_t)(bm + rg) * Kk + kc + seg * 8;
            } else {
                int row = rg - 128;
                dst = sb + PLANE + (uint32_t)row * LDSB + seg * 16;
                src = g_ct_h + (size_t)(bn + row) * Kk + kc + seg * 8;
            }
            CP_ASYNC16(dst, src);
        }
        CP_COMMIT();
    };

    prefetch(0); prefetch(1); prefetch(2);

    for (int c = 0; c < NC; c++) {
        CP_WAIT(2);               // stage c resident
        __syncthreads();
        if (c + 3 < NC) prefetch(c + 3);

        const uint32_t stg = sbase + (uint32_t)(c % NSTAGE_R) * SSTAGE_R;
        #pragma unroll
        for (int ks = 0; ks < 2; ks++) {
            uint32_t bq[4][2];
            #pragma unroll
            for (int p = 0; p < 2; p++) {
                uint32_t r = stg + PLANE + (uint32_t)(wn * 32 + p * 16) * LDSB + ks * 32 + b_off;
                ldsm4(bq[p * 2][0], bq[p * 2][1], bq[p * 2 + 1][0], bq[p * 2 + 1][1], r);
            }
            #pragma unroll
            for (int fm = 0; fm < 4; fm++) {
                uint32_t a[4];
                uint32_t r = stg + (uint32_t)(wm * 64 + fm * 16) * LDSB + ks * 32 + a_off;
                ldsm4(a[0], a[1], a[2], a[3], r);
                #pragma unroll
                for (int fn = 0; fn < 4; fn++)
                    mma_f16(acc[fm][fn], a[0], a[1], a[2], a[3], bq[fn][0], bq[fn][1]);
            }
        }
    }

    CP_WAIT(0);
    __syncthreads();

    float* epi = (float*)smc;
    #pragma unroll
    for (int fm = 0; fm < 4; fm++) {
        int r0 = wm * 64 + fm * 16 + g;
        #pragma unroll
        for (int fn = 0; fn < 4; fn++) {
            int cc = wn * 32 + fn * 8 + 2 * tig;
            *(float2*)&epi[r0 * EPI_LD + cc]       = make_float2(acc[fm][fn][0], acc[fm][fn][1]);
            *(float2*)&epi[(r0 + 8) * EPI_LD + cc] = make_float2(acc[fm][fn][2], acc[fm][fn][3]);
        }
    }
    __syncthreads();
    #pragma unroll
    for (int i = 0; i < 16; i++) {
        int idx = tid + i * 256;
        int row = idx >> 5, c4 = (idx & 31) * 4;
        float4 v = *(float4*)&epi[row * EPI_LD + c4];
        *(float4*)(out + (size_t)(bm + row) * Dd + bn + c4) = v;
    }
}

// ───────── softmax(-alpha*d) → fp32 out + fp16 scratch ─────────
__global__ void softmax_kernel(const float* __restrict__ dist, float* __restrict__ soft) {
    __shared__ float sm[32];
    size_t row = blockIdx.x;
    int t = threadIdx.x;
    float4 v = ((const float4*)(dist + row * Kk))[t];
    float m = block_reduce(fminf(fminf(v.x, v.y), fminf(v.z, v.w)), sm, 1);
    float4 e;
    e.x = expf(-ALPHA * (v.x - m));
    e.y = expf(-ALPHA * (v.y - m));
    e.z = expf(-ALPHA * (v.z - m));
    e.w = expf(-ALPHA * (v.w - m));
    float s = block_reduce(e.x + e.y + e.z + e.w, sm, 0);
    float inv = 1.0f / s;
    e.x *= inv; e.y *= inv; e.z *= inv; e.w *= inv;
    ((float4*)(soft + row * Kk))[t] = e;
    __half2 h0 = __float22half2_rn(make_float2(e.x, e.y));
    __half2 h1 = __float22half2_rn(make_float2(e.z, e.w));
    uint2 pk;
    pk.x = *(uint32_t*)&h0; pk.y = *(uint32_t*)&h1;
    ((uint2*)(g_sa_h + row * Kk))[t] = pk;
}

// ───────── launch ─────────
extern "C" void kernel_launch(void* const* d_in, const int* in_sizes, int n_in,
                              void* d_out, int out_size) {
    const float* x = (const float*)d_in[0];
    const float* w = (const float*)d_in[1];
    const float* b = (const float*)d_in[2];
    const float* C = (const float*)d_in[3];

    float* out  = (float*)d_out;
    float* dist = out;
    float* soft = out + (size_t)Nn * Kk;
    float* rec  = out + 2 * (size_t)Nn * Kk;

    cudaFuncSetAttribute(dist_gemm, cudaFuncAttributeMaxDynamicSharedMemorySize, DSMEM_D);
    cudaFuncSetAttribute(rec_gemm,  cudaFuncAttributeMaxDynamicSharedMemorySize, DSMEM_R);

    ln_kernel<<<Nn, 128>>>(x, w, b);
    c2_kernel<<<Kk, 128>>>(C);
    transpose_c<<<dim3(Dd / 32, Kk / 32), dim3(32, 8)>>>(C);

    dist_gemm<<<dim3(Kk / BN, Nn / BM), 256, DSMEM_D>>>(dist);
    softmax_kernel<<<Nn, 256>>>(dist, soft);
    rec_gemm<<<dim3(Dd / BN, Nn / BM), 256, DSMEM_R>>>(rec);
}

// round 17
// speedup vs baseline: 1.6307x; 1.0749x over previous
#include <cuda_runtime.h>
#include <cuda_bf16.h>
#include <cuda_fp16.h>
#include <cstdint>
#include <math.h>

#define Nn 131072
#define Dd 512
#define Kk 1024
#define ALPHA 32.0f
#define EPS 1e-5f

// Common tiling
#define BM 128
#define BN 128
#define KC 32
#define EPI_LD 132              // epilogue f32 row stride (528 B, 16B-aligned)

// dist: pad-free swizzled planes, 3 stages, 2 CTAs/SM
#define PLANE_D 8192            // 128 rows x 64 B (KC=32 bf16), XOR-swizzled
#define SSTAGE_D (4 * PLANE_D)  // Ahi, Alo, Bhi, Blo = 32768
#define NSTAGE_D 3
#define DSMEM_D (NSTAGE_D * SSTAGE_D)   // 98304 (2 CTAs -> 196608 <= 228KB; epi 67584 fits)

// rec: padded planes (LDSB=80), 4 stages (unchanged from R16)
#define LDSB 80
#define PLANE_R (128 * LDSB)    // 10240
#define SSTAGE_R (2 * PLANE_R)  // 20480
#define NSTAGE_R 4
#define DSMEM_R (NSTAGE_R * SSTAGE_R)  // 81920

// swizzle: permute 16B groups within the 64B row space, conflict-free for ldmatrix
#define SWZ(off, row) ((off) ^ ((((row) >> 1) & 3) << 4))

// Scratch (only referenced from DEVICE code)
__device__ float g_x2[Nn];
__device__ float g_c2[Kk];
__device__ __nv_bfloat16 g_xa_hi[(size_t)Nn * Dd];   // xn hi/lo (N x D)
__device__ __nv_bfloat16 g_xa_lo[(size_t)Nn * Dd];
__device__ __nv_bfloat16 g_cb_hi[(size_t)Kk * Dd];   // C hi/lo (K x D)
__device__ __nv_bfloat16 g_cb_lo[(size_t)Kk * Dd];
__device__ __half g_ct_h[(size_t)Dd * Kk];           // C^T fp16 (D x K)
__device__ __half g_sa_h[(size_t)Nn * Kk];           // soft fp16 (N x K)

// ───────── helpers ─────────
__device__ __forceinline__ uint32_t smem_u32(const void* p) {
    uint32_t a;
    asm("{ .reg .u64 t; cvta.to.shared.u64 t, %1; cvt.u32.u64 %0, t; }" : "=r"(a) : "l"(p));
    return a;
}
#define CP_ASYNC16(dst, src) \
    asm volatile("cp.async.cg.shared.global [%0], [%1], 16;" :: "r"(dst), "l"(src))
#define CP_COMMIT() asm volatile("cp.async.commit_group;" ::: "memory")
#define CP_WAIT(n)  asm volatile("cp.async.wait_group %0;" :: "n"(n) : "memory")

__device__ __forceinline__ void ldsm4(uint32_t& r0, uint32_t& r1, uint32_t& r2, uint32_t& r3,
                                      uint32_t addr) {
    asm volatile("ldmatrix.sync.aligned.m8n8.x4.shared.b16 {%0,%1,%2,%3}, [%4];"
                 : "=r"(r0), "=r"(r1), "=r"(r2), "=r"(r3) : "r"(addr));
}
__device__ __forceinline__ void mma_bf16(float* c, uint32_t a0, uint32_t a1, uint32_t a2,
                                         uint32_t a3, uint32_t b0, uint32_t b1) {
    asm volatile("mma.sync.aligned.m16n8k16.row.col.f32.bf16.bf16.f32 "
                 "{%0,%1,%2,%3}, {%4,%5,%6,%7}, {%8,%9}, {%0,%1,%2,%3};"
                 : "+f"(c[0]), "+f"(c[1]), "+f"(c[2]), "+f"(c[3])
                 : "r"(a0), "r"(a1), "r"(a2), "r"(a3), "r"(b0), "r"(b1));
}
__device__ __forceinline__ void mma_f16(float* c, uint32_t a0, uint32_t a1, uint32_t a2,
                                        uint32_t a3, uint32_t b0, uint32_t b1) {
    asm volatile("mma.sync.aligned.m16n8k16.row.col.f32.f16.f16.f32 "
                 "{%0,%1,%2,%3}, {%4,%5,%6,%7}, {%8,%9}, {%0,%1,%2,%3};"
                 : "+f"(c[0]), "+f"(c[1]), "+f"(c[2]), "+f"(c[3])
                 : "r"(a0), "r"(a1), "r"(a2), "r"(a3), "r"(b0), "r"(b1));
}
// bf16 hi/lo split of 4 floats
__device__ __forceinline__ void split4(float4 v, uint2& h, uint2& l) {
    __nv_bfloat16 h0 = __float2bfloat16(v.x), h1 = __float2bfloat16(v.y);
    __nv_bfloat16 h2 = __float2bfloat16(v.z), h3 = __float2bfloat16(v.w);
    __nv_bfloat16 l0 = __float2bfloat16(v.x - __bfloat162float(h0));
    __nv_bfloat16 l1 = __float2bfloat16(v.y - __bfloat162float(h1));
    __nv_bfloat16 l2 = __float2bfloat16(v.z - __bfloat162float(h2));
    __nv_bfloat16 l3 = __float2bfloat16(v.w - __bfloat162float(h3));
    __nv_bfloat162 a = __halves2bfloat162(h0, h1), b = __halves2bfloat162(h2, h3);
    __nv_bfloat162 c = __halves2bfloat162(l0, l1), d = __halves2bfloat162(l2, l3);
    h.x = *(uint32_t*)&a; h.y = *(uint32_t*)&b;
    l.x = *(uint32_t*)&c; l.y = *(uint32_t*)&d;
}

__device__ __forceinline__ float block_reduce(float v, float* sm, int op) {
    int lane = threadIdx.x & 31, wid = threadIdx.x >> 5;
    #pragma unroll
    for (int o = 16; o; o >>= 1) {
        float t = __shfl_xor_sync(0xffffffffu, v, o);
        v = op ? fminf(v, t) : (v + t);
    }
    if (lane == 0) sm[wid] = v;
    __syncthreads();
    int nw = blockDim.x >> 5;
    if (wid == 0) {
        float r = (lane < nw) ? sm[lane] : (op ? 3.4e38f : 0.0f);
        #pragma unroll
        for (int o = 16; o; o >>= 1) {
            float t = __shfl_xor_sync(0xffffffffu, r, o);
            r = op ? fminf(r, t) : (r + t);
        }
        if (lane == 0) sm[0] = r;
    }
    __syncthreads();
    float r = sm[0];
    __syncthreads();
    return r;
}

// ───────── layernorm → bf16 hi/lo + ||xn||² ─────────
__global__ void ln_kernel(const float* __restrict__ x, const float* __restrict__ w,
                          const float* __restrict__ b) {
    __shared__ float sm[32];
    size_t row = blockIdx.x;
    int t = threadIdx.x;
    float4 v = ((const float4*)(x + row * Dd))[t];
    float s = block_reduce(v.x + v.y + v.z + v.w, sm, 0);
    float mean = s * (1.0f / Dd);
    float d0 = v.x - mean, d1 = v.y - mean, d2 = v.z - mean, d3 = v.w - mean;
    float sq = block_reduce(d0 * d0 + d1 * d1 + d2 * d2 + d3 * d3, sm, 0);
    float inv = 1.0f / (sqrtf(sq * (1.0f / Dd)) + EPS);
    float4 wv = ((const float4*)w)[t];
    float4 bv = ((const float4*)b)[t];
    float4 o;
    o.x = d0 * inv * wv.x + bv.x;  o.y = d1 * inv * wv.y + bv.y;
    o.z = d2 * inv * wv.z + bv.z;  o.w = d3 * inv * wv.w + bv.w;
    float n2 = block_reduce(o.x * o.x + o.y * o.y + o.z * o.z + o.w * o.w, sm, 0);
    if (t == 0) g_x2[row] = n2;
    uint2 h, l;
    split4(o, h, l);
    ((uint2*)(g_xa_hi + row * Dd))[t] = h;
    ((uint2*)(g_xa_lo + row * Dd))[t] = l;
}

// ───────── center norms + C hi/lo ─────────
__global__ void c2_kernel(const float* __restrict__ C) {
    __shared__ float sm[32];
    size_t row = blockIdx.x;
    int t = threadIdx.x;
    float4 v = ((const float4*)(C + row * Dd))[t];
    float s = block_reduce(v.x * v.x + v.y * v.y + v.z * v.z + v.w * v.w, sm, 0);
    if (t == 0) g_c2[row] = s;
    uint2 h, l;
    split4(v, h, l);
    ((uint2*)(g_cb_hi + row * Dd))[t] = h;
    ((uint2*)(g_cb_lo + row * Dd))[t] = l;
}

// ───────── transpose C → C^T fp16 (D x K) ─────────
__global__ void transpose_c(const float* __restrict__ C) {
    __shared__ float t[32][33];
    int x = blockIdx.x * 32 + threadIdx.x;   // d
    int y = blockIdx.y * 32 + threadIdx.y;   // k
    #pragma unroll
    for (int j = 0; j < 4; j++)
        t[threadIdx.y + j * 8][threadIdx.x] = C[(size_t)(y + j * 8) * Dd + x];
    __syncthreads();
    int x2 = blockIdx.y * 32 + threadIdx.x;  // k
    int y2 = blockIdx.x * 32 + threadIdx.y;  // d
    #pragma unroll
    for (int j = 0; j < 4; j++)
        g_ct_h[(size_t)(y2 + j * 8) * Kk + x2] = __float2half(t[threadIdx.x][threadIdx.y + j * 8]);
}

// ───────── dist GEMM: bf16x3, swizzled planes, 3-stage cp.async, 2 CTAs/SM ─────────
__global__ void __launch_bounds__(256, 2)
dist_gemm(float* __restrict__ out) {
    extern __shared__ char smc[];
    const uint32_t sbase = smem_u32(smc);
    const int tid = threadIdx.x;
    const int wid = tid >> 5, lane = tid & 31;
    const int g = lane >> 2, tig = lane & 3;
    const int wm = wid & 1, wn = wid >> 1;
    const int bm = blockIdx.y * BM;
    const int bn = blockIdx.x * BN;
    constexpr int NC = Dd / KC;   // 16

    // ldmatrix lane decomposition (row within 16-row tile, 16B selector)
    const int a_lr = lane & 15, a_sel = lane >> 4;
    const int bmat = lane >> 3, brow = lane & 7;
    const int b_lr = (bmat >> 1) * 8 + brow, b_sel = bmat & 1;

    float acc[4][4][4];
    #pragma unroll
    for (int i = 0; i < 4; i++)
        #pragma unroll
        for (int j = 0; j < 4; j++)
            #pragma unroll
            for (int q = 0; q < 4; q++) acc[i][j][q] = 0.0f;

    auto prefetch = [&](int c) {
        uint32_t sb = sbase + (uint32_t)(c % NSTAGE_D) * SSTAGE_D;
        int kc = c * KC;
        #pragma unroll
        for (int i = 0; i < 8; i++) {
            int idx = tid + i * 256;                 // 0..2047
            int pl = idx >> 9, r = idx & 511;
            int row = r >> 2, seg = r & 3;
            uint32_t off = (uint32_t)row * 64 + seg * 16;
            uint32_t dst = sb + (uint32_t)pl * PLANE_D + SWZ(off, row);
            const __nv_bfloat16* src;
            if (pl == 0)      src = g_xa_hi + (size_t)(bm + row) * Dd + kc + seg * 8;
            else if (pl == 1) src = g_xa_lo + (size_t)(bm + row) * Dd + kc + seg * 8;
            else if (pl == 2) src = g_cb_hi + (size_t)(bn + row) * Dd + kc + seg * 8;
            else              src = g_cb_lo + (size_t)(bn + row) * Dd + kc + seg * 8;
            CP_ASYNC16(dst, src);
        }
        CP_COMMIT();
    };

    prefetch(0);
    prefetch(1);

    for (int c = 0; c < NC; c++) {
        CP_WAIT(1);               // stage c resident (next stage may be in flight)
        __syncthreads();          // all warps done reading stage (c-1) before overwrite
        if (c + 2 < NC) prefetch(c + 2);

        const uint32_t stg = sbase + (uint32_t)(c % NSTAGE_D) * SSTAGE_D;
        #pragma unroll
        for (int ks = 0; ks < 2; ks++) {
            uint32_t bh[4][2], bl[4][2];
            #pragma unroll
            for (int p = 0; p < 2; p++) {
                int row = wn * 32 + p * 16 + b_lr;
                uint32_t off = (uint32_t)row * 64 + ks * 32 + b_sel * 16;
                uint32_t r = stg + 2 * PLANE_D + SWZ(off, row);
                ldsm4(bh[p * 2][0], bh[p * 2][1], bh[p * 2 + 1][0], bh[p * 2 + 1][1], r);
                ldsm4(bl[p * 2][0], bl[p * 2][1], bl[p * 2 + 1][0], bl[p * 2 + 1][1], r + PLANE_D);
            }
            #pragma unroll
            for (int fp = 0; fp < 2; fp++) {
                uint32_t ah[2][4], al[2][4];
                #pragma unroll
                for (int f = 0; f < 2; f++) {
                    int fm = fp * 2 + f;
                    int row = wm * 64 + fm * 16 + a_lr;
                    uint32_t off = (uint32_t)row * 64 + ks * 32 + a_sel * 16;
                    uint32_t r = stg + SWZ(off, row);
                    ldsm4(ah[f][0], ah[f][1], ah[f][2], ah[f][3], r);
                    ldsm4(al[f][0], al[f][1], al[f][2], al[f][3], r + PLANE_D);
                }
                #pragma unroll
                for (int f = 0; f < 2; f++)
                    #pragma unroll
                    for (int fn = 0; fn < 4; fn++)
                        mma_bf16(acc[fp * 2 + f][fn], ah[f][0], ah[f][1], ah[f][2], ah[f][3],
                                 bh[fn][0], bh[fn][1]);
                #pragma unroll
                for (int f = 0; f < 2; f++)
                    #pragma unroll
                    for (int fn = 0; fn < 4; fn++)
                        mma_bf16(acc[fp * 2 + f][fn], ah[f][0], ah[f][1], ah[f][2], ah[f][3],
                                 bl[fn][0], bl[fn][1]);
                #pragma unroll
                for (int f = 0; f < 2; f++)
                    #pragma unroll
                    for (int fn = 0; fn < 4; fn++)
                        mma_bf16(acc[fp * 2 + f][fn], al[f][0], al[f][1], al[f][2], al[f][3],
                                 bh[fn][0], bh[fn][1]);
            }
        }
    }

    CP_WAIT(0);
    __syncthreads();

    float* epi = (float*)smc;
    #pragma unroll
    for (int fm = 0; fm < 4; fm++) {
        int r0 = wm * 64 + fm * 16 + g;
        #pragma unroll
        for (int fn = 0; fn < 4; fn++) {
            int cc = wn * 32 + fn * 8 + 2 * tig;
            *(float2*)&epi[r0 * EPI_LD + cc]       = make_float2(acc[fm][fn][0], acc[fm][fn][1]);
            *(float2*)&epi[(r0 + 8) * EPI_LD + cc] = make_float2(acc[fm][fn][2], acc[fm][fn][3]);
        }
    }
    __syncthreads();
    #pragma unroll
    for (int i = 0; i < 16; i++) {
        int idx = tid + i * 256;
        int row = idx >> 5, c4 = (idx & 31) * 4;
        float4 v = *(float4*)&epi[row * EPI_LD + c4];
        float x2v = g_x2[bm + row];
        v.x = sqrtf(fmaxf(x2v + g_c2[bn + c4 + 0] - 2.0f * v.x, 0.0f));
        v.y = sqrtf(fmaxf(x2v + g_c2[bn + c4 + 1] - 2.0f * v.y, 0.0f));
        v.z = sqrtf(fmaxf(x2v + g_c2[bn + c4 + 2] - 2.0f * v.z, 0.0f));
        v.w = sqrtf(fmaxf(x2v + g_c2[bn + c4 + 3] - 2.0f * v.w, 0.0f));
        *(float4*)(out + (size_t)(bm + row) * Kk + bn + c4) = v;
    }
}

// ───────── rec GEMM: fp16 single pass, ldmatrix, 4-stage cp.async, 2 CTAs/SM ─────────
__global__ void __launch_bounds__(256, 2)
rec_gemm(float* __restrict__ out) {
    extern __shared__ char smc[];
    const uint32_t sbase = smem_u32(smc);
    const int tid = threadIdx.x;
    const int wid = tid >> 5, lane = tid & 31;
    const int g = lane >> 2, tig = lane & 3;
    const int wm = wid & 1, wn = wid >> 1;
    const int bm = blockIdx.y * BM;
    const int bn = blockIdx.x * BN;
    constexpr int NC = Kk / KC;   // 32

    const uint32_t a_off = (uint32_t)(lane & 15) * LDSB + (uint32_t)(lane >> 4) * 16;
    const int bmat = lane >> 3, brow = lane & 7;
    const uint32_t b_off = (uint32_t)((bmat >> 1) * 8 + brow) * LDSB + (uint32_t)(bmat & 1) * 16;

    float acc[4][4][4];
    #pragma unroll
    for (int i = 0; i < 4; i++)
        #pragma unroll
        for (int j = 0; j < 4; j++)
            #pragma unroll
            for (int q = 0; q < 4; q++) acc[i][j][q] = 0.0f;

    auto prefetch = [&](int c) {
        uint32_t sb = sbase + (uint32_t)(c % NSTAGE_R) * SSTAGE_R;
        int kc = c * KC;
        #pragma unroll
        for (int i = 0; i < 4; i++) {
            int idx = tid + i * 256;
            int rg = idx >> 2, seg = idx & 3;
            const __half* src;
            uint32_t dst;
            if (rg < 128) {
                dst = sb + (uint32_t)rg * LDSB + seg * 16;
                src = g_sa_h + (size_t)(bm + rg) * Kk + kc + seg * 8;
            } else {
                int row = rg - 128;
                dst = sb + PLANE_R + (uint32_t)row * LDSB + seg * 16;
                src = g_ct_h + (size_t)(bn + row) * Kk + kc + seg * 8;
            }
            CP_ASYNC16(dst, src);
        }
        CP_COMMIT();
    };

    prefetch(0); prefetch(1); prefetch(2);

    for (int c = 0; c < NC; c++) {
        CP_WAIT(2);
        __syncthreads();
        if (c + 3 < NC) prefetch(c + 3);

        const uint32_t stg = sbase + (uint32_t)(c % NSTAGE_R) * SSTAGE_R;
        #pragma unroll
        for (int ks = 0; ks < 2; ks++) {
            uint32_t bq[4][2];
            #pragma unroll
            for (int p = 0; p < 2; p++) {
                uint32_t r = stg + PLANE_R + (uint32_t)(wn * 32 + p * 16) * LDSB + ks * 32 + b_off;
                ldsm4(bq[p * 2][0], bq[p * 2][1], bq[p * 2 + 1][0], bq[p * 2 + 1][1], r);
            }
            #pragma unroll
            for (int fm = 0; fm < 4; fm++) {
                uint32_t a[4];
                uint32_t r = stg + (uint32_t)(wm * 64 + fm * 16) * LDSB + ks * 32 + a_off;
                ldsm4(a[0], a[1], a[2], a[3], r);
                #pragma unroll
                for (int fn = 0; fn < 4; fn++)
                    mma_f16(acc[fm][fn], a[0], a[1], a[2], a[3], bq[fn][0], bq[fn][1]);
            }
        }
    }

    CP_WAIT(0);
    __syncthreads();

    float* epi = (float*)smc;
    #pragma unroll
    for (int fm = 0; fm < 4; fm++) {
        int r0 = wm * 64 + fm * 16 + g;
        #pragma unroll
        for (int fn = 0; fn < 4; fn++) {
            int cc = wn * 32 + fn * 8 + 2 * tig;
            *(float2*)&epi[r0 * EPI_LD + cc]       = make_float2(acc[fm][fn][0], acc[fm][fn][1]);
            *(float2*)&epi[(r0 + 8) * EPI_LD + cc] = make_float2(acc[fm][fn][2], acc[fm][fn][3]);
        }
    }
    __syncthreads();
    #pragma unroll
    for (int i = 0; i < 16; i++) {
        int idx = tid + i * 256;
        int row = idx >> 5, c4 = (idx & 31) * 4;
        float4 v = *(float4*)&epi[row * EPI_LD + c4];
        *(float4*)(out + (size_t)(bm + row) * Dd + bn + c4) = v;
    }
}

// ───────── softmax(-alpha*d) → fp32 out + fp16 scratch ─────────
__global__ void softmax_kernel(const float* __restrict__ dist, float* __restrict__ soft) {
    __shared__ float sm[32];
    size_t row = blockIdx.x;
    int t = threadIdx.x;
    float4 v = ((const float4*)(dist + row * Kk))[t];
    float m = block_reduce(fminf(fminf(v.x, v.y), fminf(v.z, v.w)), sm, 1);
    float4 e;
    e.x = expf(-ALPHA * (v.x - m));
    e.y = expf(-ALPHA * (v.y - m));
    e.z = expf(-ALPHA * (v.z - m));
    e.w = expf(-ALPHA * (v.w - m));
    float s = block_reduce(e.x + e.y + e.z + e.w, sm, 0);
    float inv = 1.0f / s;
    e.x *= inv; e.y *= inv; e.z *= inv; e.w *= inv;
    ((float4*)(soft + row * Kk))[t] = e;
    __half2 h0 = __float22half2_rn(make_float2(e.x, e.y));
    __half2 h1 = __float22half2_rn(make_float2(e.z, e.w));
    uint2 pk;
    pk.x = *(uint32_t*)&h0; pk.y = *(uint32_t*)&h1;
    ((uint2*)(g_sa_h + row * Kk))[t] = pk;
}

// ───────── launch ─────────
extern "C" void kernel_launch(void* const* d_in, const int* in_sizes, int n_in,
                              void* d_out, int out_size) {
    const float* x = (const float*)d_in[0];
    const float* w = (const float*)d_in[1];
    const float* b = (const float*)d_in[2];
    const float* C = (const float*)d_in[3];

    float* out  = (float*)d_out;
    float* dist = out;
    float* soft = out + (size_t)Nn * Kk;
    float* rec  = out + 2 * (size_t)Nn * Kk;

    cudaFuncSetAttribute(dist_gemm, cudaFuncAttributeMaxDynamicSharedMemorySize, DSMEM_D);
    cudaFuncSetAttribute(rec_gemm,  cudaFuncAttributeMaxDynamicSharedMemorySize, DSMEM_R);

    ln_kernel<<<Nn, 128>>>(x, w, b);
    c2_kernel<<<Kk, 128>>>(C);
    transpose_c<<<dim3(Dd / 32, Kk / 32), dim3(32, 8)>>>(C);

    dist_gemm<<<dim3(Kk / BN, Nn / BM), 256, DSMEM_D>>>(dist);
    softmax_kernel<<<Nn, 256>>>(dist, soft);
    rec_gemm<<<dim3(Dd / BN, Nn / BM), 256, DSMEM_R>>>(rec);
}